// round 4
// baseline (speedup 1.0000x reference)
#include <cuda_runtime.h>
#include <cstdint>

#define NN 50000
#define EE 800000

// ---------------- static device scratch (no runtime alloc allowed) ----------
__device__ float g_bufA[(size_t)NN * 512];
__device__ float g_bufB[(size_t)NN * 512];
__device__ float g_agg [(size_t)NN * 256];
__device__ int   g_deg[NN];
__device__ float g_deg_inv[NN];
__device__ int   g_row_off[NN + 1];
__device__ int   g_fill[NN];
__device__ int   g_csr_src[EE];

// ---------------- graph build ----------------------------------------------
__global__ void k_zero_deg() {
    int i = blockIdx.x * blockDim.x + threadIdx.x;
    if (i < NN) g_deg[i] = 0;
}

__global__ void k_count_deg(const int* __restrict__ dst) {
    int e = blockIdx.x * blockDim.x + threadIdx.x;
    if (e < EE) atomicAdd(&g_deg[dst[e]], 1);
}

__global__ void k_scan_deg() {
    __shared__ int sh[1024];
    __shared__ int carry;
    int t = threadIdx.x;
    if (t == 0) carry = 0;
    __syncthreads();
    for (int base = 0; base < NN; base += 1024) {
        int i = base + t;
        int v = (i < NN) ? g_deg[i] : 0;
        sh[t] = v;
        __syncthreads();
        #pragma unroll
        for (int off = 1; off < 1024; off <<= 1) {
            int tmp = (t >= off) ? sh[t - off] : 0;
            __syncthreads();
            sh[t] += tmp;
            __syncthreads();
        }
        int incl  = sh[t];
        int total = sh[1023];
        if (i < NN) {
            int excl = carry + incl - v;
            g_row_off[i] = excl;
            g_fill[i]    = excl;
            g_deg_inv[i] = 1.0f / fmaxf((float)v, 1.0f);
        }
        __syncthreads();
        if (t == 0) carry += total;
        __syncthreads();
    }
    if (t == 0) g_row_off[NN] = EE;
}

__global__ void k_fill_csr(const int* __restrict__ src, const int* __restrict__ dst) {
    int e = blockIdx.x * blockDim.x + threadIdx.x;
    if (e < EE) {
        int p = atomicAdd(&g_fill[dst[e]], 1);
        g_csr_src[p] = src[e];
    }
}

// ---------------- aggregation ------------------------------------------------
__global__ void k_aggregate(const float* __restrict__ h, float* __restrict__ agg, int din) {
    int n = blockIdx.x;
    int k = threadIdx.x;
    int s = g_row_off[n];
    int e1 = g_row_off[n + 1];
    float acc = 0.0f;
    int e = s;
    for (; e + 3 < e1; e += 4) {
        int s0 = g_csr_src[e + 0];
        int s1 = g_csr_src[e + 1];
        int s2 = g_csr_src[e + 2];
        int s3 = g_csr_src[e + 3];
        float v0 = h[(size_t)s0 * din + k];
        float v1 = h[(size_t)s1 * din + k];
        float v2 = h[(size_t)s2 * din + k];
        float v3 = h[(size_t)s3 * din + k];
        acc += (v0 + v1) + (v2 + v3);
    }
    for (; e < e1; e++) {
        int srcn = g_csr_src[e];
        acc += h[(size_t)srcn * din + k];
    }
    agg[(size_t)n * din + k] = acc * g_deg_inv[n];
}

// ---------------- mma.sync tf32 (3x-split) SAGE gemm -------------------------
// C = relu([agg|h] @ [Wl|Wr]^T + bias)
// BM=128, BK=32, BN template (128 or 64). 256 threads = 8 warps, 2x4 warp grid.
// Warp tile: 64 x (BN/4). SMEM row stride 36 floats -> conflict-free frag loads.
#define BM 128
#define BK 32
#define SA 36

// cvt.rna.tf32.f32 requires a .b32 destination
__device__ __forceinline__ uint32_t tf32_rna_bits(float x) {
    uint32_t y;
    asm("cvt.rna.tf32.f32 %0, %1;" : "=r"(y) : "f"(x));
    return y;
}
__device__ __forceinline__ void split_tf32(float v, float& hi, float& lo) {
    hi = __uint_as_float(tf32_rna_bits(v));
    lo = v - hi;
}

__device__ __forceinline__ void mma_tf32(float* c, const uint32_t* a, const uint32_t* b) {
    asm volatile(
        "mma.sync.aligned.m16n8k8.row.col.f32.tf32.tf32.f32 "
        "{%0,%1,%2,%3}, {%4,%5,%6,%7}, {%8,%9}, {%0,%1,%2,%3};"
        : "+f"(c[0]), "+f"(c[1]), "+f"(c[2]), "+f"(c[3])
        : "r"(a[0]), "r"(a[1]), "r"(a[2]), "r"(a[3]), "r"(b[0]), "r"(b[1]));
}

template<int BN>
__global__ __launch_bounds__(256, 1)
void k_gemm_mma(const float* __restrict__ A0, const float* __restrict__ A1,
                const float* __restrict__ W0, const float* __restrict__ W1,
                const float* __restrict__ bias, float* __restrict__ C,
                int din, int dout)
{
    constexpr int WN = BN / 4;   // warp tile N
    constexpr int NT = WN / 8;   // n-tiles per warp

    extern __shared__ float sm[];
    float* As_hi = sm;
    float* As_lo = sm + BM * SA;
    float* Bs_hi = sm + 2 * BM * SA;
    float* Bs_lo = Bs_hi + BN * SA;

    int tid = threadIdx.x;
    int wid = tid >> 5, lane = tid & 31;
    int wm = wid >> 2, wn = wid & 3;
    int lr = lane >> 2, lc = lane & 3;
    int rowBase = blockIdx.x * BM;
    int colBase = blockIdx.y * BN;

    float acc[4][NT][4];
    #pragma unroll
    for (int i = 0; i < 4; i++)
        #pragma unroll
        for (int j = 0; j < NT; j++)
            #pragma unroll
            for (int q = 0; q < 4; q++) acc[i][j][q] = 0.0f;

    const int K = 2 * din;
    for (int k0 = 0; k0 < K; k0 += BK) {
        const float *Ag, *Wg;
        int kk;
        if (k0 < din) { Ag = A0; Wg = W0; kk = k0; }
        else          { Ag = A1; Wg = W1; kk = k0 - din; }

        // stage A: BM x BK = 1024 float4
        for (int i = tid; i < BM * (BK / 4); i += 256) {
            int r = i >> 3;
            int c4 = (i & 7) << 2;
            float4 v = make_float4(0.f, 0.f, 0.f, 0.f);
            int gr = rowBase + r;
            if (gr < NN)
                v = *reinterpret_cast<const float4*>(&Ag[(size_t)gr * din + kk + c4]);
            float4 h4, l4;
            split_tf32(v.x, h4.x, l4.x);
            split_tf32(v.y, h4.y, l4.y);
            split_tf32(v.z, h4.z, l4.z);
            split_tf32(v.w, h4.w, l4.w);
            *reinterpret_cast<float4*>(&As_hi[r * SA + c4]) = h4;
            *reinterpret_cast<float4*>(&As_lo[r * SA + c4]) = l4;
        }
        // stage B: BN x BK
        for (int i = tid; i < BN * (BK / 4); i += 256) {
            int r = i >> 3;
            int c4 = (i & 7) << 2;
            float4 v = *reinterpret_cast<const float4*>(&Wg[(size_t)(colBase + r) * din + kk + c4]);
            float4 h4, l4;
            split_tf32(v.x, h4.x, l4.x);
            split_tf32(v.y, h4.y, l4.y);
            split_tf32(v.z, h4.z, l4.z);
            split_tf32(v.w, h4.w, l4.w);
            *reinterpret_cast<float4*>(&Bs_hi[r * SA + c4]) = h4;
            *reinterpret_cast<float4*>(&Bs_lo[r * SA + c4]) = l4;
        }
        __syncthreads();

        #pragma unroll
        for (int ks = 0; ks < BK / 8; ks++) {
            int k8 = ks * 8;
            uint32_t ah[4][4], al[4][4], bh[NT][2], bl[NT][2];
            #pragma unroll
            for (int mt = 0; mt < 4; mt++) {
                int row = wm * 64 + mt * 16 + lr;
                const float* p = &As_hi[row * SA + k8 + lc];
                const float* q = &As_lo[row * SA + k8 + lc];
                ah[mt][0] = __float_as_uint(p[0]);
                ah[mt][1] = __float_as_uint(p[8 * SA]);
                ah[mt][2] = __float_as_uint(p[4]);
                ah[mt][3] = __float_as_uint(p[8 * SA + 4]);
                al[mt][0] = __float_as_uint(q[0]);
                al[mt][1] = __float_as_uint(q[8 * SA]);
                al[mt][2] = __float_as_uint(q[4]);
                al[mt][3] = __float_as_uint(q[8 * SA + 4]);
            }
            #pragma unroll
            for (int nt = 0; nt < NT; nt++) {
                int n = wn * WN + nt * 8 + lr;
                const float* p = &Bs_hi[n * SA + k8 + lc];
                const float* q = &Bs_lo[n * SA + k8 + lc];
                bh[nt][0] = __float_as_uint(p[0]);
                bh[nt][1] = __float_as_uint(p[4]);
                bl[nt][0] = __float_as_uint(q[0]);
                bl[nt][1] = __float_as_uint(q[4]);
            }
            #pragma unroll
            for (int mt = 0; mt < 4; mt++)
                #pragma unroll
                for (int nt = 0; nt < NT; nt++) {
                    mma_tf32(acc[mt][nt], ah[mt], bh[nt]);
                    mma_tf32(acc[mt][nt], al[mt], bh[nt]);
                    mma_tf32(acc[mt][nt], ah[mt], bl[nt]);
                }
        }
        __syncthreads();
    }

    // epilogue: bias + relu + store (float2 per row-half)
    #pragma unroll
    for (int mt = 0; mt < 4; mt++) {
        int r0 = rowBase + wm * 64 + mt * 16 + lr;
        int r1 = r0 + 8;
        #pragma unroll
        for (int nt = 0; nt < NT; nt++) {
            int c = colBase + wn * WN + nt * 8 + lc * 2;
            float b0 = bias[c], b1 = bias[c + 1];
            if (r0 < NN) {
                float2 v;
                v.x = fmaxf(acc[mt][nt][0] + b0, 0.f);
                v.y = fmaxf(acc[mt][nt][1] + b1, 0.f);
                *reinterpret_cast<float2*>(&C[(size_t)r0 * dout + c]) = v;
            }
            if (r1 < NN) {
                float2 v;
                v.x = fmaxf(acc[mt][nt][2] + b0, 0.f);
                v.y = fmaxf(acc[mt][nt][3] + b1, 0.f);
                *reinterpret_cast<float2*>(&C[(size_t)r1 * dout + c]) = v;
            }
        }
    }
}

// ---------------- head: logits = h @ Wout^T + bout; softmax -----------------
__global__ void k_head(const float* __restrict__ h, const float* __restrict__ Wout,
                       const float* __restrict__ bout, float* __restrict__ out) {
    int gwarp = (blockIdx.x * blockDim.x + threadIdx.x) >> 5;
    int lane  = threadIdx.x & 31;
    if (gwarp >= NN) return;
    const float* hr = h + (size_t)gwarp * 512;
    float s[4] = {0.f, 0.f, 0.f, 0.f};
    for (int i = lane; i < 512; i += 32) {
        float hv = hr[i];
        #pragma unroll
        for (int c = 0; c < 4; c++) s[c] += hv * Wout[c * 512 + i];
    }
    #pragma unroll
    for (int off = 16; off > 0; off >>= 1)
        #pragma unroll
        for (int c = 0; c < 4; c++)
            s[c] += __shfl_xor_sync(0xFFFFFFFF, s[c], off);
    if (lane == 0) {
        float l[4];
        float m = -1e30f;
        #pragma unroll
        for (int c = 0; c < 4; c++) { l[c] = s[c] + bout[c]; m = fmaxf(m, l[c]); }
        float den = 0.f;
        #pragma unroll
        for (int c = 0; c < 4; c++) { l[c] = __expf(l[c] - m); den += l[c]; }
        float inv = 1.0f / den;
        #pragma unroll
        for (int c = 0; c < 4; c++) out[(size_t)gwarp * 4 + c] = l[c] * inv;
    }
}

// ---------------- driver -----------------------------------------------------
extern "C" void kernel_launch(void* const* d_in, const int* in_sizes, int n_in,
                              void* d_out, int out_size)
{
    const float* x    = (const float*)d_in[0];
    const float* Wl[5] = {(const float*)d_in[1],  (const float*)d_in[4],
                          (const float*)d_in[7],  (const float*)d_in[10],
                          (const float*)d_in[13]};
    const float* bl[5] = {(const float*)d_in[2],  (const float*)d_in[5],
                          (const float*)d_in[8],  (const float*)d_in[11],
                          (const float*)d_in[14]};
    const float* Wr[5] = {(const float*)d_in[3],  (const float*)d_in[6],
                          (const float*)d_in[9],  (const float*)d_in[12],
                          (const float*)d_in[15]};
    const float* Wout = (const float*)d_in[16];
    const float* bout = (const float*)d_in[17];
    const int*   ei   = (const int*)d_in[18];
    const int* src = ei;
    const int* dst = ei + EE;

    float *bufA, *bufB, *aggp;
    cudaGetSymbolAddress((void**)&bufA, g_bufA);
    cudaGetSymbolAddress((void**)&bufB, g_bufB);
    cudaGetSymbolAddress((void**)&aggp, g_agg);

    const size_t smem128 = (size_t)(2 * BM * SA + 2 * 128 * SA) * 4;  // 73728
    const size_t smem64  = (size_t)(2 * BM * SA + 2 * 64  * SA) * 4;  // 55296
    static bool attr_set = false;
    if (!attr_set) {
        cudaFuncSetAttribute(k_gemm_mma<128>, cudaFuncAttributeMaxDynamicSharedMemorySize, (int)smem128);
        cudaFuncSetAttribute(k_gemm_mma<64>,  cudaFuncAttributeMaxDynamicSharedMemorySize, (int)smem64);
        attr_set = true;
    }

    // 1. build CSR by dst
    k_zero_deg<<<(NN + 255) / 256, 256>>>();
    k_count_deg<<<(EE + 255) / 256, 256>>>(dst);
    k_scan_deg<<<1, 1024>>>();
    k_fill_csr<<<(EE + 255) / 256, 256>>>(src, dst);

    // 2. layers
    const int dins[5]  = {128, 128, 64, 128, 256};
    const int douts[5] = {128,  64, 128, 256, 512};
    const float* hcur = x;
    float* bufs[2] = {bufA, bufB};
    for (int i = 0; i < 5; i++) {
        int din = dins[i], dout = douts[i];
        k_aggregate<<<NN, din>>>(hcur, aggp, din);
        float* hnext = bufs[i & 1];
        if (dout >= 128) {
            dim3 grid((NN + BM - 1) / BM, dout / 128);
            k_gemm_mma<128><<<grid, 256, smem128>>>(aggp, hcur, Wl[i], Wr[i], bl[i], hnext, din, dout);
        } else {
            dim3 grid((NN + BM - 1) / BM, dout / 64);
            k_gemm_mma<64><<<grid, 256, smem64>>>(aggp, hcur, Wl[i], Wr[i], bl[i], hnext, din, dout);
        }
        hcur = hnext;
    }

    // 3. head + softmax
    k_head<<<(NN * 32 + 255) / 256, 256>>>(hcur, Wout, bout, (float*)d_out);
}

// round 5
// speedup vs baseline: 1.9856x; 1.9856x over previous
#include <cuda_runtime.h>
#include <cuda_fp16.h>
#include <cstdint>

#define NN 50000
#define EE 800000

// ---------------- static device scratch (no runtime alloc allowed) ----------
__device__ float g_bufA[(size_t)NN * 512];
__device__ float g_bufB[(size_t)NN * 512];
__device__ float g_agg [(size_t)NN * 256];
__device__ int   g_deg[NN];
__device__ float g_deg_inv[NN];
__device__ int   g_row_off[NN + 1];
__device__ int   g_fill[NN];
__device__ int   g_csr_src[EE];

// ---------------- graph build ----------------------------------------------
__global__ void k_zero_deg() {
    int i = blockIdx.x * blockDim.x + threadIdx.x;
    if (i < NN) g_deg[i] = 0;
}

__global__ void k_count_deg(const int* __restrict__ dst) {
    int e = blockIdx.x * blockDim.x + threadIdx.x;
    if (e < EE) atomicAdd(&g_deg[dst[e]], 1);
}

__global__ void k_scan_deg() {
    __shared__ int sh[1024];
    __shared__ int carry;
    int t = threadIdx.x;
    if (t == 0) carry = 0;
    __syncthreads();
    for (int base = 0; base < NN; base += 1024) {
        int i = base + t;
        int v = (i < NN) ? g_deg[i] : 0;
        sh[t] = v;
        __syncthreads();
        #pragma unroll
        for (int off = 1; off < 1024; off <<= 1) {
            int tmp = (t >= off) ? sh[t - off] : 0;
            __syncthreads();
            sh[t] += tmp;
            __syncthreads();
        }
        int incl  = sh[t];
        int total = sh[1023];
        if (i < NN) {
            int excl = carry + incl - v;
            g_row_off[i] = excl;
            g_fill[i]    = excl;
            g_deg_inv[i] = 1.0f / fmaxf((float)v, 1.0f);
        }
        __syncthreads();
        if (t == 0) carry += total;
        __syncthreads();
    }
    if (t == 0) g_row_off[NN] = EE;
}

__global__ void k_fill_csr(const int* __restrict__ src, const int* __restrict__ dst) {
    int e = blockIdx.x * blockDim.x + threadIdx.x;
    if (e < EE) {
        int p = atomicAdd(&g_fill[dst[e]], 1);
        g_csr_src[p] = src[e];
    }
}

// ---------------- aggregation ------------------------------------------------
__global__ void k_aggregate(const float* __restrict__ h, float* __restrict__ agg, int din) {
    int n = blockIdx.x;
    int k = threadIdx.x;
    int s = g_row_off[n];
    int e1 = g_row_off[n + 1];
    float acc = 0.0f;
    int e = s;
    for (; e + 3 < e1; e += 4) {
        int s0 = g_csr_src[e + 0];
        int s1 = g_csr_src[e + 1];
        int s2 = g_csr_src[e + 2];
        int s3 = g_csr_src[e + 3];
        float v0 = h[(size_t)s0 * din + k];
        float v1 = h[(size_t)s1 * din + k];
        float v2 = h[(size_t)s2 * din + k];
        float v3 = h[(size_t)s3 * din + k];
        acc += (v0 + v1) + (v2 + v3);
    }
    for (; e < e1; e++) {
        int srcn = g_csr_src[e];
        acc += h[(size_t)srcn * din + k];
    }
    agg[(size_t)n * din + k] = acc * g_deg_inv[n];
}

// ---------------- fp16 (3x hi/lo split) mma.sync SAGE gemm -------------------
// C = relu([agg|h] @ [Wl|Wr]^T + bias)
// BM=128, BK=32, BN template (128 or 64). 256 threads, 2x4 warp grid.
// SMEM half tiles, pitch 40 halves (20 words) -> conflict-free frag loads.
// Register prefetch of next K-chunk overlaps GMEM latency with MMA.
#define BM 128
#define BK 32
#define P32 20   /* 32-bit words per SMEM row (40 halves) */

__device__ __forceinline__ void split2(float x, float y, uint32_t& hi2, uint32_t& lo2) {
    __half hx = __float2half_rn(x);
    __half hy = __float2half_rn(y);
    float lx = x - __half2float(hx);
    float ly = y - __half2float(hy);
    __half2 h = __halves2half2(hx, hy);
    __half2 l = __halves2half2(__float2half_rn(lx), __float2half_rn(ly));
    hi2 = *reinterpret_cast<uint32_t*>(&h);
    lo2 = *reinterpret_cast<uint32_t*>(&l);
}

__device__ __forceinline__ void mma_f16(float* c, const uint32_t* a, const uint32_t* b) {
    asm volatile(
        "mma.sync.aligned.m16n8k16.row.col.f32.f16.f16.f32 "
        "{%0,%1,%2,%3}, {%4,%5,%6,%7}, {%8,%9}, {%0,%1,%2,%3};"
        : "+f"(c[0]), "+f"(c[1]), "+f"(c[2]), "+f"(c[3])
        : "r"(a[0]), "r"(a[1]), "r"(a[2]), "r"(a[3]), "r"(b[0]), "r"(b[1]));
}

template<int BN>
__global__ __launch_bounds__(256)
void k_gemm_f16(const float* __restrict__ A0, const float* __restrict__ A1,
                const float* __restrict__ W0, const float* __restrict__ W1,
                const float* __restrict__ bias, float* __restrict__ C,
                int din, int dout)
{
    constexpr int WN = BN / 4;            // warp tile N
    constexpr int NT = WN / 8;            // n-tiles per warp
    constexpr int A_IT = BM * BK / 4 / 256;   // 4
    constexpr int B_IT = BN * BK / 4 / 256;   // 4 (BN=128) or 2 (BN=64)

    __shared__ uint32_t AsH[BM * P32], AsL[BM * P32];
    __shared__ uint32_t BsH[BN * P32], BsL[BN * P32];

    int tid = threadIdx.x;
    int wid = tid >> 5, lane = tid & 31;
    int wm = wid >> 2, wn = wid & 3;
    int lr = lane >> 2, q = lane & 3;
    int rowBase = blockIdx.x * BM;
    int colBase = blockIdx.y * BN;

    float acc[4][NT][4];
    #pragma unroll
    for (int i = 0; i < 4; i++)
        #pragma unroll
        for (int j = 0; j < NT; j++)
            #pragma unroll
            for (int p = 0; p < 4; p++) acc[i][j][p] = 0.0f;

    const int K = 2 * din;
    const int nCh = K >> 5;

    float4 pa[A_IT], pb[B_IT];

    auto loadChunk = [&](int ch) {
        int k0 = ch << 5;
        const float *Ag, *Wg;
        int kk;
        if (k0 < din) { Ag = A0; Wg = W0; kk = k0; }
        else          { Ag = A1; Wg = W1; kk = k0 - din; }
        #pragma unroll
        for (int it = 0; it < A_IT; it++) {
            int i = tid + it * 256;
            int r = i >> 3, c4 = (i & 7) << 2;
            int gr = rowBase + r;
            pa[it] = (gr < NN) ? *reinterpret_cast<const float4*>(&Ag[(size_t)gr * din + kk + c4])
                               : make_float4(0.f, 0.f, 0.f, 0.f);
        }
        #pragma unroll
        for (int it = 0; it < B_IT; it++) {
            int i = tid + it * 256;
            int r = i >> 3, c4 = (i & 7) << 2;
            pb[it] = *reinterpret_cast<const float4*>(&Wg[(size_t)(colBase + r) * din + kk + c4]);
        }
    };

    loadChunk(0);

    for (int ch = 0; ch < nCh; ch++) {
        // convert + store staged regs to SMEM
        #pragma unroll
        for (int it = 0; it < A_IT; it++) {
            int i = tid + it * 256;
            int r = i >> 3, w = (i & 7) << 1;
            uint32_t h0, l0, h1, l1;
            split2(pa[it].x, pa[it].y, h0, l0);
            split2(pa[it].z, pa[it].w, h1, l1);
            AsH[r * P32 + w] = h0; AsH[r * P32 + w + 1] = h1;
            AsL[r * P32 + w] = l0; AsL[r * P32 + w + 1] = l1;
        }
        #pragma unroll
        for (int it = 0; it < B_IT; it++) {
            int i = tid + it * 256;
            int r = i >> 3, w = (i & 7) << 1;
            uint32_t h0, l0, h1, l1;
            split2(pb[it].x, pb[it].y, h0, l0);
            split2(pb[it].z, pb[it].w, h1, l1);
            BsH[r * P32 + w] = h0; BsH[r * P32 + w + 1] = h1;
            BsL[r * P32 + w] = l0; BsL[r * P32 + w + 1] = l1;
        }
        __syncthreads();

        if (ch + 1 < nCh) loadChunk(ch + 1);   // GMEM latency overlaps MMA below

        #pragma unroll
        for (int ks = 0; ks < 2; ks++) {
            int kw = ks * 8;
            uint32_t ah[4][4], al[4][4], bh[NT][2], bl[NT][2];
            #pragma unroll
            for (int mt = 0; mt < 4; mt++) {
                int row = wm * 64 + mt * 16 + lr;
                int base = row * P32 + kw + q;
                ah[mt][0] = AsH[base];
                ah[mt][1] = AsH[base + 8 * P32];
                ah[mt][2] = AsH[base + 4];
                ah[mt][3] = AsH[base + 8 * P32 + 4];
                al[mt][0] = AsL[base];
                al[mt][1] = AsL[base + 8 * P32];
                al[mt][2] = AsL[base + 4];
                al[mt][3] = AsL[base + 8 * P32 + 4];
            }
            #pragma unroll
            for (int nt = 0; nt < NT; nt++) {
                int n = wn * WN + nt * 8 + lr;
                int base = n * P32 + kw + q;
                bh[nt][0] = BsH[base];
                bh[nt][1] = BsH[base + 4];
                bl[nt][0] = BsL[base];
                bl[nt][1] = BsL[base + 4];
            }
            #pragma unroll
            for (int mt = 0; mt < 4; mt++)
                #pragma unroll
                for (int nt = 0; nt < NT; nt++) {
                    mma_f16(acc[mt][nt], ah[mt], bh[nt]);
                    mma_f16(acc[mt][nt], al[mt], bh[nt]);
                    mma_f16(acc[mt][nt], ah[mt], bl[nt]);
                }
        }
        __syncthreads();
    }

    // epilogue: bias + relu + store
    #pragma unroll
    for (int mt = 0; mt < 4; mt++) {
        int r0 = rowBase + wm * 64 + mt * 16 + lr;
        int r1 = r0 + 8;
        #pragma unroll
        for (int nt = 0; nt < NT; nt++) {
            int c = colBase + wn * WN + nt * 8 + q * 2;
            float b0 = bias[c], b1 = bias[c + 1];
            if (r0 < NN) {
                float2 v;
                v.x = fmaxf(acc[mt][nt][0] + b0, 0.f);
                v.y = fmaxf(acc[mt][nt][1] + b1, 0.f);
                *reinterpret_cast<float2*>(&C[(size_t)r0 * dout + c]) = v;
            }
            if (r1 < NN) {
                float2 v;
                v.x = fmaxf(acc[mt][nt][2] + b0, 0.f);
                v.y = fmaxf(acc[mt][nt][3] + b1, 0.f);
                *reinterpret_cast<float2*>(&C[(size_t)r1 * dout + c]) = v;
            }
        }
    }
}

// ---------------- head: logits = h @ Wout^T + bout; softmax -----------------
__global__ void k_head(const float* __restrict__ h, const float* __restrict__ Wout,
                       const float* __restrict__ bout, float* __restrict__ out) {
    int gwarp = (blockIdx.x * blockDim.x + threadIdx.x) >> 5;
    int lane  = threadIdx.x & 31;
    if (gwarp >= NN) return;
    const float* hr = h + (size_t)gwarp * 512;
    float s[4] = {0.f, 0.f, 0.f, 0.f};
    for (int i = lane; i < 512; i += 32) {
        float hv = hr[i];
        #pragma unroll
        for (int c = 0; c < 4; c++) s[c] += hv * Wout[c * 512 + i];
    }
    #pragma unroll
    for (int off = 16; off > 0; off >>= 1)
        #pragma unroll
        for (int c = 0; c < 4; c++)
            s[c] += __shfl_xor_sync(0xFFFFFFFF, s[c], off);
    if (lane == 0) {
        float l[4];
        float m = -1e30f;
        #pragma unroll
        for (int c = 0; c < 4; c++) { l[c] = s[c] + bout[c]; m = fmaxf(m, l[c]); }
        float den = 0.f;
        #pragma unroll
        for (int c = 0; c < 4; c++) { l[c] = __expf(l[c] - m); den += l[c]; }
        float inv = 1.0f / den;
        #pragma unroll
        for (int c = 0; c < 4; c++) out[(size_t)gwarp * 4 + c] = l[c] * inv;
    }
}

// ---------------- driver -----------------------------------------------------
extern "C" void kernel_launch(void* const* d_in, const int* in_sizes, int n_in,
                              void* d_out, int out_size)
{
    const float* x    = (const float*)d_in[0];
    const float* Wl[5] = {(const float*)d_in[1],  (const float*)d_in[4],
                          (const float*)d_in[7],  (const float*)d_in[10],
                          (const float*)d_in[13]};
    const float* bl[5] = {(const float*)d_in[2],  (const float*)d_in[5],
                          (const float*)d_in[8],  (const float*)d_in[11],
                          (const float*)d_in[14]};
    const float* Wr[5] = {(const float*)d_in[3],  (const float*)d_in[6],
                          (const float*)d_in[9],  (const float*)d_in[12],
                          (const float*)d_in[15]};
    const float* Wout = (const float*)d_in[16];
    const float* bout = (const float*)d_in[17];
    const int*   ei   = (const int*)d_in[18];
    const int* src = ei;
    const int* dst = ei + EE;

    float *bufA, *bufB, *aggp;
    cudaGetSymbolAddress((void**)&bufA, g_bufA);
    cudaGetSymbolAddress((void**)&bufB, g_bufB);
    cudaGetSymbolAddress((void**)&aggp, g_agg);

    // 1. build CSR by dst
    k_zero_deg<<<(NN + 255) / 256, 256>>>();
    k_count_deg<<<(EE + 255) / 256, 256>>>(dst);
    k_scan_deg<<<1, 1024>>>();
    k_fill_csr<<<(EE + 255) / 256, 256>>>(src, dst);

    // 2. layers
    const int dins[5]  = {128, 128, 64, 128, 256};
    const int douts[5] = {128,  64, 128, 256, 512};
    const float* hcur = x;
    float* bufs[2] = {bufA, bufB};
    for (int i = 0; i < 5; i++) {
        int din = dins[i], dout = douts[i];
        k_aggregate<<<NN, din>>>(hcur, aggp, din);
        float* hnext = bufs[i & 1];
        if (dout >= 128) {
            dim3 grid((NN + BM - 1) / BM, dout / 128);
            k_gemm_f16<128><<<grid, 256>>>(aggp, hcur, Wl[i], Wr[i], bl[i], hnext, din, dout);
        } else {
            dim3 grid((NN + BM - 1) / BM, 1);
            k_gemm_f16<64><<<grid, 256>>>(aggp, hcur, Wl[i], Wr[i], bl[i], hnext, din, dout);
        }
        hcur = hnext;
    }

    // 3. head + softmax
    k_head<<<(NN * 32 + 255) / 256, 256>>>(hcur, Wout, bout, (float*)d_out);
}

// round 6
// speedup vs baseline: 2.8517x; 1.4362x over previous
#include <cuda_runtime.h>
#include <cuda_fp16.h>
#include <cstdint>

#define NN 50000
#define EE 800000

// ---------------- static device scratch (no runtime alloc allowed) ----------
__device__ float g_bufA[(size_t)NN * 512];
__device__ float g_bufB[(size_t)NN * 512];
__device__ float g_agg [(size_t)NN * 256];
__device__ int   g_deg[NN];
__device__ float g_deg_inv[NN];
__device__ int   g_row_off[NN];
__device__ int   g_fill[NN];
__device__ int   g_csr_src[EE];
__device__ int   g_counter;

// ---------------- graph build ----------------------------------------------
__global__ void k_zero_deg() {
    int i = blockIdx.x * blockDim.x + threadIdx.x;
    if (i < NN) g_deg[i] = 0;
    if (i == 0) g_counter = 0;
}

__global__ void k_count_deg(const int* __restrict__ dst) {
    int e = blockIdx.x * blockDim.x + threadIdx.x;
    if (e < EE) atomicAdd(&g_deg[dst[e]], 1);
}

// parallel offsets: per-block scan + atomic base (segment order is irrelevant)
__global__ void k_offsets() {
    __shared__ int sh[256];
    __shared__ int base;
    int t = threadIdx.x;
    int i = blockIdx.x * 256 + t;
    int d = (i < NN) ? g_deg[i] : 0;
    sh[t] = d;
    __syncthreads();
    #pragma unroll
    for (int off = 1; off < 256; off <<= 1) {
        int v = (t >= off) ? sh[t - off] : 0;
        __syncthreads();
        sh[t] += v;
        __syncthreads();
    }
    int incl = sh[t];
    if (t == 255) base = atomicAdd(&g_counter, incl);
    __syncthreads();
    if (i < NN) {
        int o = base + incl - d;
        g_row_off[i] = o;
        g_fill[i]    = o;
        g_deg_inv[i] = 1.0f / fmaxf((float)d, 1.0f);
    }
}

__global__ void k_fill_csr(const int* __restrict__ src, const int* __restrict__ dst) {
    int e = blockIdx.x * blockDim.x + threadIdx.x;
    if (e < EE) {
        int p = atomicAdd(&g_fill[dst[e]], 1);
        g_csr_src[p] = src[e];
    }
}

// ---------------- aggregation (float4 lanes, multi-node blocks) -------------
__global__ void k_aggregate4(const float4* __restrict__ h4, float4* __restrict__ agg4,
                             int din4) {
    int n = blockIdx.x * blockDim.y + threadIdx.y;
    if (n >= NN) return;
    int k = threadIdx.x;               // 0..din4-1
    int s = g_row_off[n];
    int e1 = s + g_deg[n];
    float4 acc = make_float4(0.f, 0.f, 0.f, 0.f);
    int e = s;
    for (; e + 3 < e1; e += 4) {
        int s0 = g_csr_src[e + 0];
        int s1 = g_csr_src[e + 1];
        int s2 = g_csr_src[e + 2];
        int s3 = g_csr_src[e + 3];
        float4 v0 = h4[(size_t)s0 * din4 + k];
        float4 v1 = h4[(size_t)s1 * din4 + k];
        float4 v2 = h4[(size_t)s2 * din4 + k];
        float4 v3 = h4[(size_t)s3 * din4 + k];
        acc.x += (v0.x + v1.x) + (v2.x + v3.x);
        acc.y += (v0.y + v1.y) + (v2.y + v3.y);
        acc.z += (v0.z + v1.z) + (v2.z + v3.z);
        acc.w += (v0.w + v1.w) + (v2.w + v3.w);
    }
    for (; e < e1; e++) {
        float4 v = h4[(size_t)g_csr_src[e] * din4 + k];
        acc.x += v.x; acc.y += v.y; acc.z += v.z; acc.w += v.w;
    }
    float di = g_deg_inv[n];
    acc.x *= di; acc.y *= di; acc.z *= di; acc.w *= di;
    agg4[(size_t)n * din4 + k] = acc;
}

// ---------------- fp16 (3x hi/lo split) mma.sync SAGE gemm -------------------
#define BM 128
#define BK 32
#define P32 20   /* 32-bit words per SMEM row (40 halves, 80 bytes, 16B-aligned) */

__device__ __forceinline__ void split2(float x, float y, uint32_t& hi2, uint32_t& lo2) {
    __half hx = __float2half_rn(x);
    __half hy = __float2half_rn(y);
    float lx = x - __half2float(hx);
    float ly = y - __half2float(hy);
    __half2 h = __halves2half2(hx, hy);
    __half2 l = __halves2half2(__float2half_rn(lx), __float2half_rn(ly));
    hi2 = *reinterpret_cast<uint32_t*>(&h);
    lo2 = *reinterpret_cast<uint32_t*>(&l);
}

__device__ __forceinline__ void mma_f16(float* c, const uint32_t* a, const uint32_t* b) {
    asm volatile(
        "mma.sync.aligned.m16n8k16.row.col.f32.f16.f16.f32 "
        "{%0,%1,%2,%3}, {%4,%5,%6,%7}, {%8,%9}, {%0,%1,%2,%3};"
        : "+f"(c[0]), "+f"(c[1]), "+f"(c[2]), "+f"(c[3])
        : "r"(a[0]), "r"(a[1]), "r"(a[2]), "r"(a[3]), "r"(b[0]), "r"(b[1]));
}

__device__ __forceinline__ void ldm_x4(uint32_t* r, uint32_t addr) {
    asm volatile("ldmatrix.sync.aligned.m8n8.x4.shared.b16 {%0,%1,%2,%3}, [%4];"
                 : "=r"(r[0]), "=r"(r[1]), "=r"(r[2]), "=r"(r[3]) : "r"(addr));
}
__device__ __forceinline__ void ldm_x2(uint32_t* r, uint32_t addr) {
    asm volatile("ldmatrix.sync.aligned.m8n8.x2.shared.b16 {%0,%1}, [%2];"
                 : "=r"(r[0]), "=r"(r[1]) : "r"(addr));
}

template<int BN>
__global__ __launch_bounds__(256)
void k_gemm_f16(const float* __restrict__ A0, const float* __restrict__ A1,
                const float* __restrict__ W0, const float* __restrict__ W1,
                const float* __restrict__ bias, float* __restrict__ C,
                int din, int dout)
{
    constexpr int WN = BN / 4;                // warp tile N
    constexpr int NT = WN / 8;                // n-tiles per warp
    constexpr int A_IT = BM * BK / 4 / 256;   // 4
    constexpr int B_IT = BN * BK / 4 / 256;   // 4 or 2

    __shared__ uint32_t AsH[BM * P32], AsL[BM * P32];
    __shared__ uint32_t BsH[BN * P32], BsL[BN * P32];

    int tid = threadIdx.x;
    int wid = tid >> 5, lane = tid & 31;
    int wm = wid >> 2, wn = wid & 3;
    int lr = lane >> 2, q = lane & 3;
    int rowBase = blockIdx.x * BM;
    int colBase = blockIdx.y * BN;

    // ldmatrix lane addressing (bytes). A: x4 over 16x16; B: x2 over 8x16.
    int aRow = (lane & 7) + 8 * ((lane >> 3) & 1);     // row within 16-row tile
    int aCol = 16 * ((lane >> 4) & 1);                  // 0 or 16 bytes (k half)
    int bRow = lane & 7;
    int bCol = 16 * ((lane >> 3) & 1);
    uint32_t aBaseH = (uint32_t)__cvta_generic_to_shared(AsH) + (wm * 64 + aRow) * (P32 * 4) + aCol;
    uint32_t aBaseL = (uint32_t)__cvta_generic_to_shared(AsL) + (wm * 64 + aRow) * (P32 * 4) + aCol;
    uint32_t bBaseH = (uint32_t)__cvta_generic_to_shared(BsH) + (wn * WN + bRow) * (P32 * 4) + bCol;
    uint32_t bBaseL = (uint32_t)__cvta_generic_to_shared(BsL) + (wn * WN + bRow) * (P32 * 4) + bCol;

    float acc[4][NT][4];
    #pragma unroll
    for (int i = 0; i < 4; i++)
        #pragma unroll
        for (int j = 0; j < NT; j++)
            #pragma unroll
            for (int p = 0; p < 4; p++) acc[i][j][p] = 0.0f;

    const int K = 2 * din;
    const int nCh = K >> 5;

    float4 pa[A_IT], pb[B_IT];

    auto loadChunk = [&](int ch) {
        int k0 = ch << 5;
        const float *Ag, *Wg;
        int kk;
        if (k0 < din) { Ag = A0; Wg = W0; kk = k0; }
        else          { Ag = A1; Wg = W1; kk = k0 - din; }
        #pragma unroll
        for (int it = 0; it < A_IT; it++) {
            int i = tid + it * 256;
            int r = i >> 3, c4 = (i & 7) << 2;
            int gr = rowBase + r;
            pa[it] = (gr < NN) ? *reinterpret_cast<const float4*>(&Ag[(size_t)gr * din + kk + c4])
                               : make_float4(0.f, 0.f, 0.f, 0.f);
        }
        #pragma unroll
        for (int it = 0; it < B_IT; it++) {
            int i = tid + it * 256;
            int r = i >> 3, c4 = (i & 7) << 2;
            pb[it] = *reinterpret_cast<const float4*>(&Wg[(size_t)(colBase + r) * din + kk + c4]);
        }
    };

    loadChunk(0);

    for (int ch = 0; ch < nCh; ch++) {
        #pragma unroll
        for (int it = 0; it < A_IT; it++) {
            int i = tid + it * 256;
            int r = i >> 3, w = (i & 7) << 1;
            uint32_t h0, l0, h1, l1;
            split2(pa[it].x, pa[it].y, h0, l0);
            split2(pa[it].z, pa[it].w, h1, l1);
            AsH[r * P32 + w] = h0; AsH[r * P32 + w + 1] = h1;
            AsL[r * P32 + w] = l0; AsL[r * P32 + w + 1] = l1;
        }
        #pragma unroll
        for (int it = 0; it < B_IT; it++) {
            int i = tid + it * 256;
            int r = i >> 3, w = (i & 7) << 1;
            uint32_t h0, l0, h1, l1;
            split2(pb[it].x, pb[it].y, h0, l0);
            split2(pb[it].z, pb[it].w, h1, l1);
            BsH[r * P32 + w] = h0; BsH[r * P32 + w + 1] = h1;
            BsL[r * P32 + w] = l0; BsL[r * P32 + w + 1] = l1;
        }
        __syncthreads();

        if (ch + 1 < nCh) loadChunk(ch + 1);   // GMEM latency overlaps MMA below

        #pragma unroll
        for (int ks = 0; ks < 2; ks++) {
            uint32_t kb = (uint32_t)(ks * 32);
            uint32_t ah[4][4], al[4][4], bh[NT][2], bl[NT][2];
            #pragma unroll
            for (int mt = 0; mt < 4; mt++) {
                uint32_t moff = (uint32_t)(mt * 16 * P32 * 4) + kb;
                ldm_x4(ah[mt], aBaseH + moff);
                ldm_x4(al[mt], aBaseL + moff);
            }
            #pragma unroll
            for (int nt = 0; nt < NT; nt++) {
                uint32_t noff = (uint32_t)(nt * 8 * P32 * 4) + kb;
                ldm_x2(bh[nt], bBaseH + noff);
                ldm_x2(bl[nt], bBaseL + noff);
            }
            #pragma unroll
            for (int mt = 0; mt < 4; mt++)
                #pragma unroll
                for (int nt = 0; nt < NT; nt++) {
                    mma_f16(acc[mt][nt], ah[mt], bh[nt]);
                    mma_f16(acc[mt][nt], al[mt], bh[nt]);
                    mma_f16(acc[mt][nt], ah[mt], bl[nt]);
                }
        }
        __syncthreads();
    }

    // epilogue: bias + relu + store
    #pragma unroll
    for (int mt = 0; mt < 4; mt++) {
        int r0 = rowBase + wm * 64 + mt * 16 + lr;
        int r1 = r0 + 8;
        #pragma unroll
        for (int nt = 0; nt < NT; nt++) {
            int c = colBase + wn * WN + nt * 8 + q * 2;
            float b0 = bias[c], b1 = bias[c + 1];
            if (r0 < NN) {
                float2 v;
                v.x = fmaxf(acc[mt][nt][0] + b0, 0.f);
                v.y = fmaxf(acc[mt][nt][1] + b1, 0.f);
                *reinterpret_cast<float2*>(&C[(size_t)r0 * dout + c]) = v;
            }
            if (r1 < NN) {
                float2 v;
                v.x = fmaxf(acc[mt][nt][2] + b0, 0.f);
                v.y = fmaxf(acc[mt][nt][3] + b1, 0.f);
                *reinterpret_cast<float2*>(&C[(size_t)r1 * dout + c]) = v;
            }
        }
    }
}

// ---------------- head: logits = h @ Wout^T + bout; softmax -----------------
__global__ void k_head(const float* __restrict__ h, const float* __restrict__ Wout,
                       const float* __restrict__ bout, float* __restrict__ out) {
    int gwarp = (blockIdx.x * blockDim.x + threadIdx.x) >> 5;
    int lane  = threadIdx.x & 31;
    if (gwarp >= NN) return;
    const float* hr = h + (size_t)gwarp * 512;
    float s[4] = {0.f, 0.f, 0.f, 0.f};
    for (int i = lane; i < 512; i += 32) {
        float hv = hr[i];
        #pragma unroll
        for (int c = 0; c < 4; c++) s[c] += hv * Wout[c * 512 + i];
    }
    #pragma unroll
    for (int off = 16; off > 0; off >>= 1)
        #pragma unroll
        for (int c = 0; c < 4; c++)
            s[c] += __shfl_xor_sync(0xFFFFFFFF, s[c], off);
    if (lane == 0) {
        float l[4];
        float m = -1e30f;
        #pragma unroll
        for (int c = 0; c < 4; c++) { l[c] = s[c] + bout[c]; m = fmaxf(m, l[c]); }
        float den = 0.f;
        #pragma unroll
        for (int c = 0; c < 4; c++) { l[c] = __expf(l[c] - m); den += l[c]; }
        float inv = 1.0f / den;
        #pragma unroll
        for (int c = 0; c < 4; c++) out[(size_t)gwarp * 4 + c] = l[c] * inv;
    }
}

// ---------------- driver -----------------------------------------------------
extern "C" void kernel_launch(void* const* d_in, const int* in_sizes, int n_in,
                              void* d_out, int out_size)
{
    const float* x    = (const float*)d_in[0];
    const float* Wl[5] = {(const float*)d_in[1],  (const float*)d_in[4],
                          (const float*)d_in[7],  (const float*)d_in[10],
                          (const float*)d_in[13]};
    const float* bl[5] = {(const float*)d_in[2],  (const float*)d_in[5],
                          (const float*)d_in[8],  (const float*)d_in[11],
                          (const float*)d_in[14]};
    const float* Wr[5] = {(const float*)d_in[3],  (const float*)d_in[6],
                          (const float*)d_in[9],  (const float*)d_in[12],
                          (const float*)d_in[15]};
    const float* Wout = (const float*)d_in[16];
    const float* bout = (const float*)d_in[17];
    const int*   ei   = (const int*)d_in[18];
    const int* src = ei;
    const int* dst = ei + EE;

    float *bufA, *bufB, *aggp;
    cudaGetSymbolAddress((void**)&bufA, g_bufA);
    cudaGetSymbolAddress((void**)&bufB, g_bufB);
    cudaGetSymbolAddress((void**)&aggp, g_agg);

    // 1. build CSR by dst (parallel offsets, unordered segments)
    k_zero_deg<<<(NN + 255) / 256, 256>>>();
    k_count_deg<<<(EE + 255) / 256, 256>>>(dst);
    k_offsets<<<(NN + 255) / 256, 256>>>();
    k_fill_csr<<<(EE + 255) / 256, 256>>>(src, dst);

    // 2. layers
    const int dins[5]  = {128, 128, 64, 128, 256};
    const int douts[5] = {128,  64, 128, 256, 512};
    const float* hcur = x;
    float* bufs[2] = {bufA, bufB};
    for (int i = 0; i < 5; i++) {
        int din = dins[i], dout = douts[i];
        int din4 = din / 4;
        int npb = 128 / din4;                      // nodes per 128-thread block
        dim3 ablk(din4, npb);
        k_aggregate4<<<(NN + npb - 1) / npb, ablk>>>(
            (const float4*)hcur, (float4*)aggp, din4);
        float* hnext = bufs[i & 1];
        if (dout >= 128) {
            dim3 grid((NN + BM - 1) / BM, dout / 128);
            k_gemm_f16<128><<<grid, 256>>>(aggp, hcur, Wl[i], Wr[i], bl[i], hnext, din, dout);
        } else {
            dim3 grid((NN + BM - 1) / BM, 1);
            k_gemm_f16<64><<<grid, 256>>>(aggp, hcur, Wl[i], Wr[i], bl[i], hnext, din, dout);
        }
        hcur = hnext;
    }

    // 3. head + softmax
    k_head<<<(NN * 32 + 255) / 256, 256>>>(hcur, Wout, bout, (float*)d_out);
}

// round 7
// speedup vs baseline: 2.9740x; 1.0429x over previous
#include <cuda_runtime.h>
#include <cuda_fp16.h>
#include <cstdint>

#define NN 50000
#define EE 800000

// ---------------- static device scratch (no runtime alloc allowed) ----------
__device__ float g_bufA[(size_t)NN * 512];
__device__ float g_bufB[(size_t)NN * 512];
__device__ float g_agg [(size_t)NN * 256];
__device__ int   g_deg[NN];
__device__ float g_deg_inv[NN];
__device__ int   g_row_off[NN];
__device__ int   g_fill[NN];
__device__ int   g_csr_src[EE];
__device__ int   g_counter;

// ---------------- graph build ----------------------------------------------
__global__ void k_zero_deg() {
    int i = blockIdx.x * blockDim.x + threadIdx.x;
    if (i < NN) g_deg[i] = 0;
    if (i == 0) g_counter = 0;
}

__global__ void k_count_deg(const int* __restrict__ dst) {
    int e = blockIdx.x * blockDim.x + threadIdx.x;
    if (e < EE) atomicAdd(&g_deg[dst[e]], 1);
}

// parallel offsets: per-block scan + atomic base (segment order is irrelevant)
__global__ void k_offsets() {
    __shared__ int sh[256];
    __shared__ int base;
    int t = threadIdx.x;
    int i = blockIdx.x * 256 + t;
    int d = (i < NN) ? g_deg[i] : 0;
    sh[t] = d;
    __syncthreads();
    #pragma unroll
    for (int off = 1; off < 256; off <<= 1) {
        int v = (t >= off) ? sh[t - off] : 0;
        __syncthreads();
        sh[t] += v;
        __syncthreads();
    }
    int incl = sh[t];
    if (t == 255) base = atomicAdd(&g_counter, incl);
    __syncthreads();
    if (i < NN) {
        int o = base + incl - d;
        g_row_off[i] = o;
        g_fill[i]    = o;
        g_deg_inv[i] = 1.0f / fmaxf((float)d, 1.0f);
    }
}

__global__ void k_fill_csr(const int* __restrict__ src, const int* __restrict__ dst) {
    int e = blockIdx.x * blockDim.x + threadIdx.x;
    if (e < EE) {
        int p = atomicAdd(&g_fill[dst[e]], 1);
        g_csr_src[p] = src[e];
    }
}

// ---------------- aggregation (float4 lanes, multi-node blocks) -------------
__global__ void k_aggregate4(const float4* __restrict__ h4, float4* __restrict__ agg4,
                             int din4) {
    int n = blockIdx.x * blockDim.y + threadIdx.y;
    if (n >= NN) return;
    int k = threadIdx.x;               // 0..din4-1
    int s = g_row_off[n];
    int e1 = s + g_deg[n];
    float4 acc = make_float4(0.f, 0.f, 0.f, 0.f);
    int e = s;
    for (; e + 3 < e1; e += 4) {
        int s0 = g_csr_src[e + 0];
        int s1 = g_csr_src[e + 1];
        int s2 = g_csr_src[e + 2];
        int s3 = g_csr_src[e + 3];
        float4 v0 = h4[(size_t)s0 * din4 + k];
        float4 v1 = h4[(size_t)s1 * din4 + k];
        float4 v2 = h4[(size_t)s2 * din4 + k];
        float4 v3 = h4[(size_t)s3 * din4 + k];
        acc.x += (v0.x + v1.x) + (v2.x + v3.x);
        acc.y += (v0.y + v1.y) + (v2.y + v3.y);
        acc.z += (v0.z + v1.z) + (v2.z + v3.z);
        acc.w += (v0.w + v1.w) + (v2.w + v3.w);
    }
    for (; e < e1; e++) {
        float4 v = h4[(size_t)g_csr_src[e] * din4 + k];
        acc.x += v.x; acc.y += v.y; acc.z += v.z; acc.w += v.w;
    }
    float di = g_deg_inv[n];
    acc.x *= di; acc.y *= di; acc.z *= di; acc.w *= di;
    agg4[(size_t)n * din4 + k] = acc;
}

// ---------------- fp16 (3x hi/lo split) mma.sync SAGE gemm -------------------
#define BM 128
#define BK 32
#define P32 20   /* 32-bit words per SMEM row (40 halves, 80 bytes, 16B-aligned) */

__device__ __forceinline__ void split2(float x, float y, uint32_t& hi2, uint32_t& lo2) {
    __half hx = __float2half_rn(x);
    __half hy = __float2half_rn(y);
    float lx = x - __half2float(hx);
    float ly = y - __half2float(hy);
    __half2 h = __halves2half2(hx, hy);
    __half2 l = __halves2half2(__float2half_rn(lx), __float2half_rn(ly));
    hi2 = *reinterpret_cast<uint32_t*>(&h);
    lo2 = *reinterpret_cast<uint32_t*>(&l);
}

__device__ __forceinline__ void mma_f16(float* c, const uint32_t* a, const uint32_t* b) {
    asm volatile(
        "mma.sync.aligned.m16n8k16.row.col.f32.f16.f16.f32 "
        "{%0,%1,%2,%3}, {%4,%5,%6,%7}, {%8,%9}, {%0,%1,%2,%3};"
        : "+f"(c[0]), "+f"(c[1]), "+f"(c[2]), "+f"(c[3])
        : "r"(a[0]), "r"(a[1]), "r"(a[2]), "r"(a[3]), "r"(b[0]), "r"(b[1]));
}

__device__ __forceinline__ void ldm_x4(uint32_t* r, uint32_t addr) {
    asm volatile("ldmatrix.sync.aligned.m8n8.x4.shared.b16 {%0,%1,%2,%3}, [%4];"
                 : "=r"(r[0]), "=r"(r[1]), "=r"(r[2]), "=r"(r[3]) : "r"(addr));
}
__device__ __forceinline__ void ldm_x2(uint32_t* r, uint32_t addr) {
    asm volatile("ldmatrix.sync.aligned.m8n8.x2.shared.b16 {%0,%1}, [%2];"
                 : "=r"(r[0]), "=r"(r[1]) : "r"(addr));
}

template<int BN>
__global__ __launch_bounds__(256)
void k_gemm_f16(const float* __restrict__ A0, const float* __restrict__ A1,
                const float* __restrict__ W0, const float* __restrict__ W1,
                const float* __restrict__ bias, float* __restrict__ C,
                int din, int dout)
{
    constexpr int WN = BN / 4;                // warp tile N
    constexpr int NT = WN / 8;                // n-tiles per warp
    constexpr int A_IT = BM * BK / 4 / 256;   // 4
    constexpr int B_IT = BN * BK / 4 / 256;   // 4 or 2

    __shared__ uint32_t AsH[BM * P32], AsL[BM * P32];
    __shared__ uint32_t BsH[BN * P32], BsL[BN * P32];

    int tid = threadIdx.x;
    int wid = tid >> 5, lane = tid & 31;
    int wm = wid >> 2, wn = wid & 3;
    int lr = lane >> 2, q = lane & 3;
    int rowBase = blockIdx.x * BM;
    int colBase = blockIdx.y * BN;

    // ldmatrix lane addressing (bytes). A: x4 over 16x16; B: x2 over 8x16.
    int aRow = (lane & 7) + 8 * ((lane >> 3) & 1);
    int aCol = 16 * ((lane >> 4) & 1);
    int bRow = lane & 7;
    int bCol = 16 * ((lane >> 3) & 1);
    uint32_t aBaseH = (uint32_t)__cvta_generic_to_shared(AsH) + (wm * 64 + aRow) * (P32 * 4) + aCol;
    uint32_t aBaseL = (uint32_t)__cvta_generic_to_shared(AsL) + (wm * 64 + aRow) * (P32 * 4) + aCol;
    uint32_t bBaseH = (uint32_t)__cvta_generic_to_shared(BsH) + (wn * WN + bRow) * (P32 * 4) + bCol;
    uint32_t bBaseL = (uint32_t)__cvta_generic_to_shared(BsL) + (wn * WN + bRow) * (P32 * 4) + bCol;

    float acc[4][NT][4];
    #pragma unroll
    for (int i = 0; i < 4; i++)
        #pragma unroll
        for (int j = 0; j < NT; j++)
            #pragma unroll
            for (int p = 0; p < 4; p++) acc[i][j][p] = 0.0f;

    const int K = 2 * din;
    const int nCh = K >> 5;

    float4 pa[A_IT], pb[B_IT];

    auto loadChunk = [&](int ch) {
        int k0 = ch << 5;
        const float *Ag, *Wg;
        int kk;
        if (k0 < din) { Ag = A0; Wg = W0; kk = k0; }
        else          { Ag = A1; Wg = W1; kk = k0 - din; }
        #pragma unroll
        for (int it = 0; it < A_IT; it++) {
            int i = tid + it * 256;
            int r = i >> 3, c4 = (i & 7) << 2;
            int gr = rowBase + r;
            pa[it] = (gr < NN) ? *reinterpret_cast<const float4*>(&Ag[(size_t)gr * din + kk + c4])
                               : make_float4(0.f, 0.f, 0.f, 0.f);
        }
        #pragma unroll
        for (int it = 0; it < B_IT; it++) {
            int i = tid + it * 256;
            int r = i >> 3, c4 = (i & 7) << 2;
            pb[it] = *reinterpret_cast<const float4*>(&Wg[(size_t)(colBase + r) * din + kk + c4]);
        }
    };

    loadChunk(0);

    for (int ch = 0; ch < nCh; ch++) {
        #pragma unroll
        for (int it = 0; it < A_IT; it++) {
            int i = tid + it * 256;
            int r = i >> 3, w = (i & 7) << 1;
            uint32_t h0, l0, h1, l1;
            split2(pa[it].x, pa[it].y, h0, l0);
            split2(pa[it].z, pa[it].w, h1, l1);
            AsH[r * P32 + w] = h0; AsH[r * P32 + w + 1] = h1;
            AsL[r * P32 + w] = l0; AsL[r * P32 + w + 1] = l1;
        }
        #pragma unroll
        for (int it = 0; it < B_IT; it++) {
            int i = tid + it * 256;
            int r = i >> 3, w = (i & 7) << 1;
            uint32_t h0, l0, h1, l1;
            split2(pb[it].x, pb[it].y, h0, l0);
            split2(pb[it].z, pb[it].w, h1, l1);
            BsH[r * P32 + w] = h0; BsH[r * P32 + w + 1] = h1;
            BsL[r * P32 + w] = l0; BsL[r * P32 + w + 1] = l1;
        }
        __syncthreads();

        if (ch + 1 < nCh) loadChunk(ch + 1);   // GMEM latency overlaps MMA below

        #pragma unroll
        for (int ks = 0; ks < 2; ks++) {
            uint32_t kb = (uint32_t)(ks * 32);
            uint32_t ah[4][4], al[4][4], bh[NT][2], bl[NT][2];
            #pragma unroll
            for (int mt = 0; mt < 4; mt++) {
                uint32_t moff = (uint32_t)(mt * 16 * P32 * 4) + kb;
                ldm_x4(ah[mt], aBaseH + moff);
                ldm_x4(al[mt], aBaseL + moff);
            }
            #pragma unroll
            for (int nt = 0; nt < NT; nt++) {
                uint32_t noff = (uint32_t)(nt * 8 * P32 * 4) + kb;
                ldm_x2(bh[nt], bBaseH + noff);
                ldm_x2(bl[nt], bBaseL + noff);
            }
            // term-major sweeps: every acc reused at distance 4*NT independent
            // MMAs -> no RAW stall on the accumulator chain.
            #pragma unroll
            for (int mt = 0; mt < 4; mt++)
                #pragma unroll
                for (int nt = 0; nt < NT; nt++)
                    mma_f16(acc[mt][nt], ah[mt], bh[nt]);
            #pragma unroll
            for (int mt = 0; mt < 4; mt++)
                #pragma unroll
                for (int nt = 0; nt < NT; nt++)
                    mma_f16(acc[mt][nt], al[mt], bh[nt]);
            #pragma unroll
            for (int mt = 0; mt < 4; mt++)
                #pragma unroll
                for (int nt = 0; nt < NT; nt++)
                    mma_f16(acc[mt][nt], ah[mt], bl[nt]);
        }
        __syncthreads();
    }

    // epilogue: bias + relu + store
    #pragma unroll
    for (int mt = 0; mt < 4; mt++) {
        int r0 = rowBase + wm * 64 + mt * 16 + lr;
        int r1 = r0 + 8;
        #pragma unroll
        for (int nt = 0; nt < NT; nt++) {
            int c = colBase + wn * WN + nt * 8 + q * 2;
            float b0 = bias[c], b1 = bias[c + 1];
            if (r0 < NN) {
                float2 v;
                v.x = fmaxf(acc[mt][nt][0] + b0, 0.f);
                v.y = fmaxf(acc[mt][nt][1] + b1, 0.f);
                *reinterpret_cast<float2*>(&C[(size_t)r0 * dout + c]) = v;
            }
            if (r1 < NN) {
                float2 v;
                v.x = fmaxf(acc[mt][nt][2] + b0, 0.f);
                v.y = fmaxf(acc[mt][nt][3] + b1, 0.f);
                *reinterpret_cast<float2*>(&C[(size_t)r1 * dout + c]) = v;
            }
        }
    }
}

// ---------------- head: logits = h @ Wout^T + bout; softmax -----------------
__global__ void k_head(const float4* __restrict__ h4, const float4* __restrict__ Wout4,
                       const float* __restrict__ bout, float* __restrict__ out) {
    int gwarp = (blockIdx.x * blockDim.x + threadIdx.x) >> 5;
    int lane  = threadIdx.x & 31;
    if (gwarp >= NN) return;
    const float4* hr = h4 + (size_t)gwarp * 128;
    float s[4] = {0.f, 0.f, 0.f, 0.f};
    #pragma unroll
    for (int it = 0; it < 4; it++) {
        int i = lane + it * 32;
        float4 hv = hr[i];
        #pragma unroll
        for (int c = 0; c < 4; c++) {
            float4 wv = Wout4[c * 128 + i];
            s[c] += hv.x * wv.x + hv.y * wv.y + hv.z * wv.z + hv.w * wv.w;
        }
    }
    #pragma unroll
    for (int off = 16; off > 0; off >>= 1)
        #pragma unroll
        for (int c = 0; c < 4; c++)
            s[c] += __shfl_xor_sync(0xFFFFFFFF, s[c], off);
    if (lane == 0) {
        float l[4];
        float m = -1e30f;
        #pragma unroll
        for (int c = 0; c < 4; c++) { l[c] = s[c] + bout[c]; m = fmaxf(m, l[c]); }
        float den = 0.f;
        #pragma unroll
        for (int c = 0; c < 4; c++) { l[c] = __expf(l[c] - m); den += l[c]; }
        float inv = 1.0f / den;
        #pragma unroll
        for (int c = 0; c < 4; c++) out[(size_t)gwarp * 4 + c] = l[c] * inv;
    }
}

// ---------------- driver -----------------------------------------------------
extern "C" void kernel_launch(void* const* d_in, const int* in_sizes, int n_in,
                              void* d_out, int out_size)
{
    const float* x    = (const float*)d_in[0];
    const float* Wl[5] = {(const float*)d_in[1],  (const float*)d_in[4],
                          (const float*)d_in[7],  (const float*)d_in[10],
                          (const float*)d_in[13]};
    const float* bl[5] = {(const float*)d_in[2],  (const float*)d_in[5],
                          (const float*)d_in[8],  (const float*)d_in[11],
                          (const float*)d_in[14]};
    const float* Wr[5] = {(const float*)d_in[3],  (const float*)d_in[6],
                          (const float*)d_in[9],  (const float*)d_in[12],
                          (const float*)d_in[15]};
    const float* Wout = (const float*)d_in[16];
    const float* bout = (const float*)d_in[17];
    const int*   ei   = (const int*)d_in[18];
    const int* src = ei;
    const int* dst = ei + EE;

    float *bufA, *bufB, *aggp;
    cudaGetSymbolAddress((void**)&bufA, g_bufA);
    cudaGetSymbolAddress((void**)&bufB, g_bufB);
    cudaGetSymbolAddress((void**)&aggp, g_agg);

    // 1. build CSR by dst (parallel offsets, unordered segments)
    k_zero_deg<<<(NN + 255) / 256, 256>>>();
    k_count_deg<<<(EE + 255) / 256, 256>>>(dst);
    k_offsets<<<(NN + 255) / 256, 256>>>();
    k_fill_csr<<<(EE + 255) / 256, 256>>>(src, dst);

    // 2. layers
    const int dins[5]  = {128, 128, 64, 128, 256};
    const int douts[5] = {128,  64, 128, 256, 512};
    const float* hcur = x;
    float* bufs[2] = {bufA, bufB};
    for (int i = 0; i < 5; i++) {
        int din = dins[i], dout = douts[i];
        int din4 = din / 4;
        int npb = 128 / din4;                      // nodes per 128-thread block
        dim3 ablk(din4, npb);
        k_aggregate4<<<(NN + npb - 1) / npb, ablk>>>(
            (const float4*)hcur, (float4*)aggp, din4);
        float* hnext = bufs[i & 1];
        if (dout >= 128) {
            dim3 grid((NN + BM - 1) / BM, dout / 128);
            k_gemm_f16<128><<<grid, 256>>>(aggp, hcur, Wl[i], Wr[i], bl[i], hnext, din, dout);
        } else {
            dim3 grid((NN + BM - 1) / BM, 1);
            k_gemm_f16<64><<<grid, 256>>>(aggp, hcur, Wl[i], Wr[i], bl[i], hnext, din, dout);
        }
        hcur = hnext;
    }

    // 3. head + softmax
    k_head<<<(NN * 32 + 255) / 256, 256>>>((const float4*)hcur, (const float4*)Wout,
                                           bout, (float*)d_out);
}

// round 11
// speedup vs baseline: 3.1085x; 1.0452x over previous
#include <cuda_runtime.h>
#include <cuda_fp16.h>
#include <cstdint>

#define NN 50000
#define EE 800000
#define NWTOT 393216

// ---------------- static device scratch (no runtime alloc allowed) ----------
__device__ float g_bufA[(size_t)NN * 512];
__device__ float g_bufB[(size_t)NN * 512];
__device__ float g_agg [(size_t)NN * 256];
__device__ int   g_deg[NN];
__device__ float g_deg_inv[NN];
__device__ int   g_row_off[NN];
__device__ int   g_fill[NN];
__device__ int   g_csr_src[EE];
__device__ int   g_counter;
__device__ __half g_Whi[NWTOT];
__device__ __half g_Wlo[NWTOT];

// ---------------- graph build ----------------------------------------------
__global__ void k_zero_deg() {
    int i = blockIdx.x * blockDim.x + threadIdx.x;
    if (i < NN) g_deg[i] = 0;
    if (i == 0) g_counter = 0;
}

__global__ void k_count_deg(const int* __restrict__ dst) {
    int e = blockIdx.x * blockDim.x + threadIdx.x;
    if (e < EE) atomicAdd(&g_deg[dst[e]], 1);
}

__global__ void k_offsets() {
    __shared__ int sh[256];
    __shared__ int base;
    int t = threadIdx.x;
    int i = blockIdx.x * 256 + t;
    int d = (i < NN) ? g_deg[i] : 0;
    sh[t] = d;
    __syncthreads();
    #pragma unroll
    for (int off = 1; off < 256; off <<= 1) {
        int v = (t >= off) ? sh[t - off] : 0;
        __syncthreads();
        sh[t] += v;
        __syncthreads();
    }
    int incl = sh[t];
    if (t == 255) base = atomicAdd(&g_counter, incl);
    __syncthreads();
    if (i < NN) {
        int o = base + incl - d;
        g_row_off[i] = o;
        g_fill[i]    = o;
        g_deg_inv[i] = 1.0f / fmaxf((float)d, 1.0f);
    }
}

__global__ void k_fill_csr(const int* __restrict__ src, const int* __restrict__ dst) {
    int e = blockIdx.x * blockDim.x + threadIdx.x;
    if (e < EE) {
        int p = atomicAdd(&g_fill[dst[e]], 1);
        g_csr_src[p] = src[e];
    }
}

// ---------------- weight pre-conversion to fp16 hi/lo ------------------------
struct WP { const float* w[10]; };

__global__ void k_convW(WP p) {
    const int off[11] = {0, 16384, 32768, 40960, 49152, 57344,
                         65536, 98304, 131072, 262144, 393216};
    int i = blockIdx.x * 256 + threadIdx.x;
    if (i >= NWTOT) return;
    int s = 0;
    #pragma unroll
    for (int j = 1; j < 10; j++) if (i >= off[j]) s = j;
    float v = p.w[s][i - off[s]];
    __half h = __float2half_rn(v);
    g_Whi[i] = h;
    g_Wlo[i] = __float2half_rn(v - __half2float(h));
}

// ---------------- aggregation (float4 lanes, multi-node blocks) -------------
__global__ void k_aggregate4(const float4* __restrict__ h4, float4* __restrict__ agg4,
                             int din4) {
    int n = blockIdx.x * blockDim.y + threadIdx.y;
    if (n >= NN) return;
    int k = threadIdx.x;
    int s = g_row_off[n];
    int e1 = s + g_deg[n];
    float4 acc = make_float4(0.f, 0.f, 0.f, 0.f);
    int e = s;
    for (; e + 3 < e1; e += 4) {
        int s0 = g_csr_src[e + 0];
        int s1 = g_csr_src[e + 1];
        int s2 = g_csr_src[e + 2];
        int s3 = g_csr_src[e + 3];
        float4 v0 = h4[(size_t)s0 * din4 + k];
        float4 v1 = h4[(size_t)s1 * din4 + k];
        float4 v2 = h4[(size_t)s2 * din4 + k];
        float4 v3 = h4[(size_t)s3 * din4 + k];
        acc.x += (v0.x + v1.x) + (v2.x + v3.x);
        acc.y += (v0.y + v1.y) + (v2.y + v3.y);
        acc.z += (v0.z + v1.z) + (v2.z + v3.z);
        acc.w += (v0.w + v1.w) + (v2.w + v3.w);
    }
    for (; e < e1; e++) {
        float4 v = h4[(size_t)g_csr_src[e] * din4 + k];
        acc.x += v.x; acc.y += v.y; acc.z += v.z; acc.w += v.w;
    }
    float di = g_deg_inv[n];
    acc.x *= di; acc.y *= di; acc.z *= di; acc.w *= di;
    agg4[(size_t)n * din4 + k] = acc;
}

// ---------------- fp16 (3x hi/lo split) mma.sync SAGE gemm -------------------
#define BM 128
#define BK 32
#define P32 20   /* words per SMEM row: 40 halves, 80 B (16B-aligned pitch) */

__device__ __forceinline__ void split2p(float x, float y, uint32_t& hi2, uint32_t& lo2) {
    asm("cvt.rn.f16x2.f32 %0, %1, %2;" : "=r"(hi2) : "f"(y), "f"(x));
    float hx, hy;
    asm("{\n\t.reg .b16 l, h;\n\tmov.b32 {l, h}, %2;\n\t"
        "cvt.f32.f16 %0, l;\n\tcvt.f32.f16 %1, h;\n\t}"
        : "=f"(hx), "=f"(hy) : "r"(hi2));
    float lx = x - hx, ly = y - hy;
    asm("cvt.rn.f16x2.f32 %0, %1, %2;" : "=r"(lo2) : "f"(ly), "f"(lx));
}

__device__ __forceinline__ void mma_f16(float* c, const uint32_t* a, const uint32_t* b) {
    asm volatile(
        "mma.sync.aligned.m16n8k16.row.col.f32.f16.f16.f32 "
        "{%0,%1,%2,%3}, {%4,%5,%6,%7}, {%8,%9}, {%0,%1,%2,%3};"
        : "+f"(c[0]), "+f"(c[1]), "+f"(c[2]), "+f"(c[3])
        : "r"(a[0]), "r"(a[1]), "r"(a[2]), "r"(a[3]), "r"(b[0]), "r"(b[1]));
}

__device__ __forceinline__ void ldm_x4(uint32_t* r, uint32_t addr) {
    asm volatile("ldmatrix.sync.aligned.m8n8.x4.shared.b16 {%0,%1,%2,%3}, [%4];"
                 : "=r"(r[0]), "=r"(r[1]), "=r"(r[2]), "=r"(r[3]) : "r"(addr));
}
__device__ __forceinline__ void ldm_x2(uint32_t* r, uint32_t addr) {
    asm volatile("ldmatrix.sync.aligned.m8n8.x2.shared.b16 {%0,%1}, [%2];"
                 : "=r"(r[0]), "=r"(r[1]) : "r"(addr));
}

template<int BN>
__global__ __launch_bounds__(256)
void k_gemm_f16(const float* __restrict__ A0, const float* __restrict__ A1,
                const __half* __restrict__ WhiL, const __half* __restrict__ WloL,
                const __half* __restrict__ WhiR, const __half* __restrict__ WloR,
                const float* __restrict__ bias, float* __restrict__ C,
                int din, int dout)
{
    constexpr int WN = BN / 4;
    constexpr int NT = WN / 8;
    constexpr int A_IT = BM * BK / 4 / 256;   // 4 float4 loads / thread
    constexpr int B_IT = BN * 4 / 256;        // uint4 (8-half) loads: 2 or 1

    __shared__ uint32_t AsH[BM * P32], AsL[BM * P32];
    __shared__ uint32_t BsH[BN * P32], BsL[BN * P32];

    int tid = threadIdx.x;
    int wid = tid >> 5, lane = tid & 31;
    int wm = wid >> 2, wn = wid & 3;
    int lr = lane >> 2, q = lane & 3;
    int rowBase = blockIdx.x * BM;
    int colBase = blockIdx.y * BN;

    // ldmatrix lane byte addresses
    int aRow = (lane & 7) + 8 * ((lane >> 3) & 1);
    int aCol = 16 * ((lane >> 4) & 1);
    int bRow = lane & 7;
    int bCol = 16 * ((lane >> 3) & 1);
    uint32_t aBaseH = (uint32_t)__cvta_generic_to_shared(AsH) + (wm * 64 + aRow) * 80 + aCol;
    uint32_t aBaseL = (uint32_t)__cvta_generic_to_shared(AsL) + (wm * 64 + aRow) * 80 + aCol;
    uint32_t bBaseH = (uint32_t)__cvta_generic_to_shared(BsH) + (wn * WN + bRow) * 80 + bCol;
    uint32_t bBaseL = (uint32_t)__cvta_generic_to_shared(BsL) + (wn * WN + bRow) * 80 + bCol;

    float acc[4][NT][4];
    #pragma unroll
    for (int i = 0; i < 4; i++)
        #pragma unroll
        for (int j = 0; j < NT; j++)
            #pragma unroll
            for (int p = 0; p < 4; p++) acc[i][j][p] = 0.0f;

    const int K = 2 * din;
    const int nCh = K >> 5;

    float4 pa[A_IT];
    uint4 pbh[B_IT], pbl[B_IT];

    auto loadChunk = [&](int ch) {
        int k0 = ch << 5;
        const float* Ag;
        const __half *Bh, *Bl;
        int kk;
        if (k0 < din) { Ag = A0; Bh = WhiL; Bl = WloL; kk = k0; }
        else          { Ag = A1; Bh = WhiR; Bl = WloR; kk = k0 - din; }
        #pragma unroll
        for (int it = 0; it < A_IT; it++) {
            int i = tid + it * 256;
            int r = i >> 3, c4 = (i & 7) << 2;
            int gr = rowBase + r;
            pa[it] = (gr < NN) ? *reinterpret_cast<const float4*>(&Ag[(size_t)gr * din + kk + c4])
                               : make_float4(0.f, 0.f, 0.f, 0.f);
        }
        #pragma unroll
        for (int it = 0; it < B_IT; it++) {
            int i = tid + it * 256;
            int r = i >> 2, c8 = (i & 3) << 3;
            size_t goff = (size_t)(colBase + r) * din + kk + c8;
            pbh[it] = *reinterpret_cast<const uint4*>(&Bh[goff]);
            pbl[it] = *reinterpret_cast<const uint4*>(&Bl[goff]);
        }
    };

    loadChunk(0);

    for (int ch = 0; ch < nCh; ch++) {
        // stage A (packed cvt split)
        #pragma unroll
        for (int it = 0; it < A_IT; it++) {
            int i = tid + it * 256;
            int r = i >> 3, w = (i & 7) << 1;
            uint32_t h0, l0, h1, l1;
            split2p(pa[it].x, pa[it].y, h0, l0);
            split2p(pa[it].z, pa[it].w, h1, l1);
            AsH[r * P32 + w] = h0; AsH[r * P32 + w + 1] = h1;
            AsL[r * P32 + w] = l0; AsL[r * P32 + w + 1] = l1;
        }
        // stage B (pure copy of pre-converted weights)
        #pragma unroll
        for (int it = 0; it < B_IT; it++) {
            int i = tid + it * 256;
            int r = i >> 2, w4 = (i & 3) << 2;
            *reinterpret_cast<uint4*>(&BsH[r * P32 + w4]) = pbh[it];
            *reinterpret_cast<uint4*>(&BsL[r * P32 + w4]) = pbl[it];
        }
        __syncthreads();

        if (ch + 1 < nCh) loadChunk(ch + 1);   // GMEM latency overlaps MMA

        #pragma unroll
        for (int ks = 0; ks < 2; ks++) {
            uint32_t kb = (uint32_t)(ks * 32);
            uint32_t ah[4][4], al[4][4], bh[NT][2], bl[NT][2];
            #pragma unroll
            for (int mt = 0; mt < 4; mt++) {
                uint32_t moff = (uint32_t)(mt * 16 * 80) + kb;
                ldm_x4(ah[mt], aBaseH + moff);
                ldm_x4(al[mt], aBaseL + moff);
            }
            #pragma unroll
            for (int nt = 0; nt < NT; nt++) {
                uint32_t noff = (uint32_t)(nt * 8 * 80) + kb;
                ldm_x2(bh[nt], bBaseH + noff);
                ldm_x2(bl[nt], bBaseL + noff);
            }
            #pragma unroll
            for (int mt = 0; mt < 4; mt++)
                #pragma unroll
                for (int nt = 0; nt < NT; nt++)
                    mma_f16(acc[mt][nt], ah[mt], bh[nt]);
            #pragma unroll
            for (int mt = 0; mt < 4; mt++)
                #pragma unroll
                for (int nt = 0; nt < NT; nt++)
                    mma_f16(acc[mt][nt], al[mt], bh[nt]);
            #pragma unroll
            for (int mt = 0; mt < 4; mt++)
                #pragma unroll
                for (int nt = 0; nt < NT; nt++)
                    mma_f16(acc[mt][nt], ah[mt], bl[nt]);
        }
        __syncthreads();
    }

    // epilogue: bias + relu + store
    #pragma unroll
    for (int mt = 0; mt < 4; mt++) {
        int r0 = rowBase + wm * 64 + mt * 16 + lr;
        int r1 = r0 + 8;
        #pragma unroll
        for (int nt = 0; nt < NT; nt++) {
            int c = colBase + wn * WN + nt * 8 + q * 2;
            float b0 = bias[c], b1 = bias[c + 1];
            if (r0 < NN) {
                float2 v;
                v.x = fmaxf(acc[mt][nt][0] + b0, 0.f);
                v.y = fmaxf(acc[mt][nt][1] + b1, 0.f);
                *reinterpret_cast<float2*>(&C[(size_t)r0 * dout + c]) = v;
            }
            if (r1 < NN) {
                float2 v;
                v.x = fmaxf(acc[mt][nt][2] + b0, 0.f);
                v.y = fmaxf(acc[mt][nt][3] + b1, 0.f);
                *reinterpret_cast<float2*>(&C[(size_t)r1 * dout + c]) = v;
            }
        }
    }
}

// ---------------- head: logits = h @ Wout^T + bout; softmax -----------------
__global__ void k_head(const float4* __restrict__ h4, const float4* __restrict__ Wout4,
                       const float* __restrict__ bout, float* __restrict__ out) {
    int gwarp = (blockIdx.x * blockDim.x + threadIdx.x) >> 5;
    int lane  = threadIdx.x & 31;
    if (gwarp >= NN) return;
    const float4* hr = h4 + (size_t)gwarp * 128;
    float s[4] = {0.f, 0.f, 0.f, 0.f};
    #pragma unroll
    for (int it = 0; it < 4; it++) {
        int i = lane + it * 32;
        float4 hv = hr[i];
        #pragma unroll
        for (int c = 0; c < 4; c++) {
            float4 wv = Wout4[c * 128 + i];
            s[c] += hv.x * wv.x + hv.y * wv.y + hv.z * wv.z + hv.w * wv.w;
        }
    }
    #pragma unroll
    for (int off = 16; off > 0; off >>= 1)
        #pragma unroll
        for (int c = 0; c < 4; c++)
            s[c] += __shfl_xor_sync(0xFFFFFFFF, s[c], off);
    if (lane == 0) {
        float l[4];
        float m = -1e30f;
        #pragma unroll
        for (int c = 0; c < 4; c++) { l[c] = s[c] + bout[c]; m = fmaxf(m, l[c]); }
        float den = 0.f;
        #pragma unroll
        for (int c = 0; c < 4; c++) { l[c] = __expf(l[c] - m); den += l[c]; }
        float inv = 1.0f / den;
        #pragma unroll
        for (int c = 0; c < 4; c++) out[(size_t)gwarp * 4 + c] = l[c] * inv;
    }
}

// ---------------- driver -----------------------------------------------------
extern "C" void kernel_launch(void* const* d_in, const int* in_sizes, int n_in,
                              void* d_out, int out_size)
{
    const float* x    = (const float*)d_in[0];
    const float* Wl[5] = {(const float*)d_in[1],  (const float*)d_in[4],
                          (const float*)d_in[7],  (const float*)d_in[10],
                          (const float*)d_in[13]};
    const float* bl[5] = {(const float*)d_in[2],  (const float*)d_in[5],
                          (const float*)d_in[8],  (const float*)d_in[11],
                          (const float*)d_in[14]};
    const float* Wr[5] = {(const float*)d_in[3],  (const float*)d_in[6],
                          (const float*)d_in[9],  (const float*)d_in[12],
                          (const float*)d_in[15]};
    const float* Wout = (const float*)d_in[16];
    const float* bout = (const float*)d_in[17];
    const int*   ei   = (const int*)d_in[18];
    const int* src = ei;
    const int* dst = ei + EE;

    float *bufA, *bufB, *aggp;
    __half *whi, *wlo;
    cudaGetSymbolAddress((void**)&bufA, g_bufA);
    cudaGetSymbolAddress((void**)&bufB, g_bufB);
    cudaGetSymbolAddress((void**)&aggp, g_agg);
    cudaGetSymbolAddress((void**)&whi, g_Whi);
    cudaGetSymbolAddress((void**)&wlo, g_Wlo);

    // 0. convert weights to fp16 hi/lo once per call
    WP wp;
    for (int i = 0; i < 5; i++) { wp.w[2 * i] = Wl[i]; wp.w[2 * i + 1] = Wr[i]; }
    k_convW<<<(NWTOT + 255) / 256, 256>>>(wp);

    // 1. build CSR by dst
    k_zero_deg<<<(NN + 255) / 256, 256>>>();
    k_count_deg<<<(EE + 255) / 256, 256>>>(dst);
    k_offsets<<<(NN + 255) / 256, 256>>>();
    k_fill_csr<<<(EE + 255) / 256, 256>>>(src, dst);

    // 2. layers
    const int dins[5]  = {128, 128, 64, 128, 256};
    const int douts[5] = {128,  64, 128, 256, 512};
    const int woff[10] = {0, 16384, 32768, 40960, 49152, 57344,
                          65536, 98304, 131072, 262144};
    const float* hcur = x;
    float* bufs[2] = {bufA, bufB};
    for (int i = 0; i < 5; i++) {
        int din = dins[i], dout = douts[i];
        int din4 = din / 4;
        int npb = 128 / din4;
        dim3 ablk(din4, npb);
        k_aggregate4<<<(NN + npb - 1) / npb, ablk>>>(
            (const float4*)hcur, (float4*)aggp, din4);
        float* hnext = bufs[i & 1];
        const __half* whl = whi + woff[2 * i];
        const __half* wll = wlo + woff[2 * i];
        const __half* whr = whi + woff[2 * i + 1];
        const __half* wlr = wlo + woff[2 * i + 1];
        if (dout >= 128) {
            dim3 grid((NN + BM - 1) / BM, dout / 128);
            k_gemm_f16<128><<<grid, 256>>>(aggp, hcur, whl, wll, whr, wlr,
                                           bl[i], hnext, din, dout);
        } else {
            dim3 grid((NN + BM - 1) / BM, 1);
            k_gemm_f16<64><<<grid, 256>>>(aggp, hcur, whl, wll, whr, wlr,
                                          bl[i], hnext, din, dout);
        }
        hcur = hnext;
    }

    // 3. head + softmax
    k_head<<<(NN * 32 + 255) / 256, 256>>>((const float4*)hcur, (const float4*)Wout,
                                           bout, (float*)d_out);
}